// round 14
// baseline (speedup 1.0000x reference)
#include <cuda_runtime.h>
#include <cuda_bf16.h>
#include <cuda_fp16.h>
#include <math.h>
#include <stdint.h>

#define Tn 524288
#define Bn 4096
#define Hn 512
#define Vn 100000
#define EPS 1e-5f

// Scratch (device globals)
__device__ __half d_embh[(size_t)Vn * Hn];         // 102.4 MB fp16 table
__device__ __nv_bfloat16 d_bowh[(size_t)Bn * Hn];  // 4 MB
__device__ __nv_bfloat16 d_bowl[(size_t)Bn * Hn];  // 4 MB
__device__ __nv_bfloat16 d_W1h[(size_t)Hn * Hn];   // 512 KB
__device__ __nv_bfloat16 d_W1l[(size_t)Hn * Hn];   // 512 KB
__device__ float d_z[(size_t)Bn * Hn];             // 8 MB
__device__ float d_ps[32][Hn];
__device__ float d_pq[32][Hn];
__device__ float d_mu[Hn];
__device__ float d_A[Hn];                          // invstd * gamma
__device__ unsigned int d_ctr;                     // GEMM CTA arrival counter
__device__ unsigned int d_ctr2;                    // logits CTA arrival counter
__device__ int   d_segstart[Bn + 1];

// ---------------------------------------------------------------------------
// Kernel 0: prep = bounds detect + W1 -> bf16 hi/lo + emb -> fp16.
// Blocks [0,2048): bounds. [2048,2560): W1. [2560,2560+6400): emb convert.
// ---------------------------------------------------------------------------
#define EMB_F4 ((size_t)Vn * Hn / 4)   // 12.8M float4
#define EMB_BLKS 6400

__global__ __launch_bounds__(256)
void prep_kernel(const int* __restrict__ seg, const float* __restrict__ W1,
                 const float* __restrict__ emb) {
    int b = blockIdx.x;
    if (b < 2048) {
        int i = b * 256 + threadIdx.x;
        int cur = seg[i];
        int prev = (i == 0) ? -1 : seg[i - 1];
        for (int s = prev + 1; s <= cur; s++) d_segstart[s] = i;
        if (i == Tn - 1)
            for (int s = cur + 1; s <= Bn; s++) d_segstart[s] = Tn;
    } else if (b < 2560) {
        int i = (b - 2048) * 256 + threadIdx.x;  // float2 id over W1
        float2 v = ((const float2*)W1)[i];
        __nv_bfloat162 h = __floats2bfloat162_rn(v.x, v.y);
        __nv_bfloat162 l = __floats2bfloat162_rn(v.x - __bfloat162float(h.x),
                                                 v.y - __bfloat162float(h.y));
        ((__nv_bfloat162*)d_W1h)[i] = h;
        ((__nv_bfloat162*)d_W1l)[i] = l;
    } else {
        size_t blk = b - 2560;
#pragma unroll
        for (int j = 0; j < 8; j++) {
            size_t fi = blk * 2048 + j * 256 + threadIdx.x;
            if (fi < EMB_F4) {
                float4 v = ((const float4*)emb)[fi];
                __half2 p2[2];
                p2[0] = __floats2half2_rn(v.x, v.y);
                p2[1] = __floats2half2_rn(v.z, v.w);
                ((uint2*)d_embh)[fi] = *reinterpret_cast<uint2*>(p2);
            }
        }
    }
}

// ---------------------------------------------------------------------------
// Kernel 1: embedding-bag (segment mean) over the fp16 table.
// One block per segment; thread c owns 4 columns (uint2 = 4 halves / token).
// ---------------------------------------------------------------------------
__global__ __launch_bounds__(128)
void bag_kernel(const int* __restrict__ tokens) {
    int b = blockIdx.x;
    int start = d_segstart[b];
    int end   = d_segstart[b + 1];

    int c = threadIdx.x;   // uint2 index within row (0..127)
    float4 acc[4];
#pragma unroll
    for (int u = 0; u < 4; u++) acc[u] = make_float4(0.f, 0.f, 0.f, 0.f);

    for (int i = start; i < end; i += 8) {
        int rem = end - i;
        int tok[8];
        float w[8];
#pragma unroll
        for (int u = 0; u < 8; u++) {
            bool ok = (u < rem);
            tok[u] = tokens[ok ? (i + u) : i];
            w[u] = ok ? 1.0f : 0.0f;
        }
        uint2 raw[8];
#pragma unroll
        for (int u = 0; u < 8; u++)
            raw[u] = ((const uint2*)(d_embh + (size_t)tok[u] * Hn))[c];
#pragma unroll
        for (int u = 0; u < 8; u++) {
            __half2* h2 = reinterpret_cast<__half2*>(&raw[u]);
            float2 f0 = __half22float2(h2[0]);
            float2 f1 = __half22float2(h2[1]);
            float4& a = acc[u & 3];
            a.x = fmaf(f0.x, w[u], a.x);
            a.y = fmaf(f0.y, w[u], a.y);
            a.z = fmaf(f1.x, w[u], a.z);
            a.w = fmaf(f1.y, w[u], a.w);
        }
    }

#pragma unroll
    for (int u = 2; u > 0; u >>= 1)
#pragma unroll
        for (int q = 0; q < u; q++) {
            acc[q].x += acc[q + u].x; acc[q].y += acc[q + u].y;
            acc[q].z += acc[q + u].z; acc[q].w += acc[q + u].w;
        }

    float inv = 1.0f / fmaxf((float)(end - start), 1.0f);
    float4 r;
    r.x = acc[0].x * inv; r.y = acc[0].y * inv;
    r.z = acc[0].z * inv; r.w = acc[0].w * inv;

    __nv_bfloat162 hxy = __floats2bfloat162_rn(r.x, r.y);
    __nv_bfloat162 hzw = __floats2bfloat162_rn(r.z, r.w);
    __nv_bfloat162 lxy = __floats2bfloat162_rn(r.x - __bfloat162float(hxy.x),
                                               r.y - __bfloat162float(hxy.y));
    __nv_bfloat162 lzw = __floats2bfloat162_rn(r.z - __bfloat162float(hzw.x),
                                               r.w - __bfloat162float(hzw.y));
    size_t base = (size_t)b * Hn + c * 4;
    *(__nv_bfloat162*)(d_bowh + base)     = hxy;
    *(__nv_bfloat162*)(d_bowh + base + 2) = hzw;
    *(__nv_bfloat162*)(d_bowl + base)     = lxy;
    *(__nv_bfloat162*)(d_bowl + base + 2) = lzw;
}

// ---------------------------------------------------------------------------
// Kernel 2: bf16 split tensor-core GEMM, single-wave (128 CTAs, 512 threads),
// 4-stage cp.async pipeline, fused stats + last-CTA finalize.
// ---------------------------------------------------------------------------
#define GM 128
#define GN 128
#define KT 32
#define NT_K (Hn / KT)
#define LDAS 40
#define ASZ (GM * LDAS)
#define BSZ (GN * LDAS)
#define STAGES 4
#define GEMM_SMEM ((2 * ASZ + 2 * BSZ) * STAGES * 2)   // 163840 bytes

__device__ __forceinline__ void cpa16(__nv_bfloat16* dst, const __nv_bfloat16* src) {
    uint32_t d = (uint32_t)__cvta_generic_to_shared(dst);
    asm volatile("cp.async.cg.shared.global [%0], [%1], 16;" :: "r"(d), "l"(src) : "memory");
}

__device__ __forceinline__ void ldsm_x4(uint32_t* r, const __nv_bfloat16* p) {
    uint32_t addr = (uint32_t)__cvta_generic_to_shared(p);
    asm volatile("ldmatrix.sync.aligned.m8n8.x4.shared.b16 {%0,%1,%2,%3}, [%4];"
                 : "=r"(r[0]), "=r"(r[1]), "=r"(r[2]), "=r"(r[3]) : "r"(addr));
}

__device__ __forceinline__ void mma_bf16(float* c, const uint32_t* a, const uint32_t* b) {
    asm volatile(
        "mma.sync.aligned.m16n8k16.row.col.f32.bf16.bf16.f32 "
        "{%0,%1,%2,%3}, {%4,%5,%6,%7}, {%8,%9}, {%0,%1,%2,%3};"
        : "+f"(c[0]), "+f"(c[1]), "+f"(c[2]), "+f"(c[3])
        : "r"(a[0]), "r"(a[1]), "r"(a[2]), "r"(a[3]), "r"(b[0]), "r"(b[1]));
}

__global__ __launch_bounds__(512)
void gemm_kernel(const float* __restrict__ b1, const float* __restrict__ gamma) {
    extern __shared__ __nv_bfloat16 sm[];
    __nv_bfloat16* AhB = sm;
    __nv_bfloat16* AlB = sm + STAGES * ASZ;
    __nv_bfloat16* BhB = sm + 2 * STAGES * ASZ;
    __nv_bfloat16* BlB = sm + 2 * STAGES * ASZ + STAGES * BSZ;
    __shared__ unsigned int sLast;

    int tid = threadIdx.x;
    int lane = tid & 31;
    int warp = tid >> 5;
    int wm = warp & 3;
    int wn = warp >> 2;
    int g = lane >> 2;
    int cc = lane & 3;
    int tile = lane >> 3;
    int rr = lane & 7;

    int rowBase = blockIdx.x * GM;
    int colBase = blockIdx.y * GN;

    float acc[2][4][4];
#pragma unroll
    for (int mt = 0; mt < 2; mt++)
#pragma unroll
        for (int nt = 0; nt < 4; nt++)
#pragma unroll
            for (int q = 0; q < 4; q++) acc[mt][nt][q] = 0.f;

    auto stageTile = [&](int it) {
        int buf = it % STAGES;
        int k0 = it * KT;
        __nv_bfloat16* Ah = AhB + buf * ASZ;
        __nv_bfloat16* Al = AlB + buf * ASZ;
        __nv_bfloat16* Bh = BhB + buf * BSZ;
        __nv_bfloat16* Bl = BlB + buf * BSZ;
        int r = tid >> 2;
        int q = tid & 3;
        size_t srcA = (size_t)(rowBase + r) * Hn + k0 + q * 8;
        cpa16(Ah + r * LDAS + q * 8, d_bowh + srcA);
        cpa16(Al + r * LDAS + q * 8, d_bowl + srcA);
        size_t srcB = (size_t)(colBase + r) * Hn + k0 + q * 8;
        cpa16(Bh + r * LDAS + q * 8, d_W1h + srcB);
        cpa16(Bl + r * LDAS + q * 8, d_W1l + srcB);
        asm volatile("cp.async.commit_group;" ::: "memory");
    };

    auto computeTile = [&](int it) {
        int buf = it % STAGES;
        const __nv_bfloat16* Ah = AhB + buf * ASZ;
        const __nv_bfloat16* Al = AlB + buf * ASZ;
        const __nv_bfloat16* Bh = BhB + buf * BSZ;
        const __nv_bfloat16* Bl = BlB + buf * BSZ;
#pragma unroll
        for (int kk = 0; kk < 2; kk++) {
            int kb = kk * 16;
            int ar_off = (tile & 1) * 8 + rr;
            int ak = kb + (tile >> 1) * 8;
            uint32_t afh[2][4], afl[2][4];
#pragma unroll
            for (int mt = 0; mt < 2; mt++) {
                int row = wm * 32 + mt * 16 + ar_off;
                ldsm_x4(afh[mt], Ah + row * LDAS + ak);
                ldsm_x4(afl[mt], Al + row * LDAS + ak);
            }
            int br_off = (tile >> 1) * 8 + rr;
            int bk = kb + (tile & 1) * 8;
            uint32_t bfh[2][4], bfl[2][4];
#pragma unroll
            for (int np = 0; np < 2; np++) {
                int row = wn * 32 + np * 16 + br_off;
                ldsm_x4(bfh[np], Bh + row * LDAS + bk);
                ldsm_x4(bfl[np], Bl + row * LDAS + bk);
            }
#pragma unroll
            for (int mt = 0; mt < 2; mt++)
#pragma unroll
                for (int nt = 0; nt < 4; nt++) {
                    const uint32_t* bh = &bfh[nt >> 1][(nt & 1) * 2];
                    const uint32_t* bl = &bfl[nt >> 1][(nt & 1) * 2];
                    mma_bf16(acc[mt][nt], afl[mt], bh);
                    mma_bf16(acc[mt][nt], afh[mt], bl);
                    mma_bf16(acc[mt][nt], afh[mt], bh);
                }
        }
    };

    stageTile(0);
    stageTile(1);
    stageTile(2);
    asm volatile("cp.async.wait_group 2;" ::: "memory");
    __syncthreads();

    for (int it = 0; it < NT_K; it++) {
        computeTile(it);
        if (it == NT_K - 1) break;
        if (it + 3 < NT_K) {
            stageTile(it + 3);
            asm volatile("cp.async.wait_group 2;" ::: "memory");
        } else if (it + 2 < NT_K) {
            asm volatile("cp.async.wait_group 1;" ::: "memory");
        } else {
            asm volatile("cp.async.wait_group 0;" ::: "memory");
        }
        __syncthreads();
    }
    __syncthreads();

    // ---- epilogue: bias + store z + fused column-stat partials ----
    float* sS = (float*)sm;
    float* sQ = (float*)sm + 512;

    float colS[4][2];
    float colQ[4][2];
#pragma unroll
    for (int nt = 0; nt < 4; nt++)
        colS[nt][0] = colS[nt][1] = colQ[nt][0] = colQ[nt][1] = 0.f;

#pragma unroll
    for (int mt = 0; mt < 2; mt++) {
#pragma unroll
        for (int nt = 0; nt < 4; nt++) {
            int col = colBase + wn * 32 + nt * 8 + cc * 2;
            float b0 = b1[col], b1v = b1[col + 1];
            int row0 = rowBase + wm * 32 + mt * 16 + g;
            float2 o0, o1;
            o0.x = acc[mt][nt][0] + b0;
            o0.y = acc[mt][nt][1] + b1v;
            o1.x = acc[mt][nt][2] + b0;
            o1.y = acc[mt][nt][3] + b1v;
            *(float2*)(d_z + (size_t)row0 * Hn + col) = o0;
            *(float2*)(d_z + (size_t)(row0 + 8) * Hn + col) = o1;
            colS[nt][0] += o0.x + o1.x;
            colS[nt][1] += o0.y + o1.y;
            colQ[nt][0] += o0.x * o0.x + o1.x * o1.x;
            colQ[nt][1] += o0.y * o0.y + o1.y * o1.y;
        }
    }
#pragma unroll
    for (int o = 4; o <= 16; o <<= 1) {
#pragma unroll
        for (int nt = 0; nt < 4; nt++) {
#pragma unroll
            for (int p = 0; p < 2; p++) {
                colS[nt][p] += __shfl_xor_sync(0xFFFFFFFFu, colS[nt][p], o);
                colQ[nt][p] += __shfl_xor_sync(0xFFFFFFFFu, colQ[nt][p], o);
            }
        }
    }
    if (g == 0) {
#pragma unroll
        for (int nt = 0; nt < 4; nt++) {
#pragma unroll
            for (int p = 0; p < 2; p++) {
                sS[(wn * 4 + wm) * 32 + nt * 8 + cc * 2 + p] = colS[nt][p];
                sQ[(wn * 4 + wm) * 32 + nt * 8 + cc * 2 + p] = colQ[nt][p];
            }
        }
    }
    __syncthreads();
    if (tid < GN) {
        int cwn = tid >> 5;
        int ci = tid & 31;
        float s = 0.f, q = 0.f;
#pragma unroll
        for (int y = 0; y < 4; y++) {
            s += sS[(cwn * 4 + y) * 32 + ci];
            q += sQ[(cwn * 4 + y) * 32 + ci];
        }
        d_ps[blockIdx.x][colBase + tid] = s;
        d_pq[blockIdx.x][colBase + tid] = q;
    }

    __threadfence();
    if (tid == 0) sLast = (atomicAdd(&d_ctr, 1u) == 127u) ? 1u : 0u;
    __syncthreads();
    if (sLast) {
        __threadfence();
        int c = tid;
        if (c < Hn) {
            float s = 0.f, q = 0.f;
#pragma unroll
            for (int y = 0; y < 32; y++) { s += d_ps[y][c]; q += d_pq[y][c]; }
            float mu = s * (1.0f / Bn);
            float var = q * (1.0f / Bn) - mu * mu;
            d_mu[c] = mu;
            d_A[c] = rsqrtf(var + EPS) * gamma[c];
        }
        __threadfence();
        if (tid == 0) d_ctr = 0;
    }
}

// ---------------------------------------------------------------------------
// Kernel 3: normalize + ReLU + dot(w2) -> logits, fused BCE loss in last CTA.
// 512 blocks x 256 threads; one warp per row.
// ---------------------------------------------------------------------------
__global__ __launch_bounds__(256)
void logits_kernel(const float* __restrict__ beta,
                   const float* __restrict__ w2,
                   const float* __restrict__ b2,
                   const float* __restrict__ t,
                   float* __restrict__ out) {
    __shared__ unsigned int sLast;
    __shared__ float sred[256];

    int tid = threadIdx.x;
    int warp = tid >> 5;
    int lane = tid & 31;

    int row = blockIdx.x * 8 + warp;
    const float4* zr = (const float4*)(d_z + (size_t)row * Hn);
    float sum = 0.f;
#pragma unroll
    for (int q = 0; q < 4; q++) {
        int c4 = lane + 32 * q;
        float4 z  = zr[c4];
        float4 mu = ((const float4*)d_mu)[c4];
        float4 a  = ((const float4*)d_A)[c4];
        float4 be = ((const float4*)beta)[c4];
        float4 w  = ((const float4*)w2)[c4];
        sum += fmaxf((z.x - mu.x) * a.x + be.x, 0.f) * w.x;
        sum += fmaxf((z.y - mu.y) * a.y + be.y, 0.f) * w.y;
        sum += fmaxf((z.z - mu.z) * a.z + be.z, 0.f) * w.z;
        sum += fmaxf((z.w - mu.w) * a.w + be.w, 0.f) * w.w;
    }
#pragma unroll
    for (int o = 16; o > 0; o >>= 1) sum += __shfl_xor_sync(0xFFFFFFFFu, sum, o);
    if (lane == 0) out[1 + row] = sum + b2[0];

    __threadfence();
    if (tid == 0) sLast = (atomicAdd(&d_ctr2, 1u) == 511u) ? 1u : 0u;
    __syncthreads();
    if (sLast) {
        __threadfence();
        float acc = 0.f;
#pragma unroll
        for (int i = tid; i < Bn; i += 256) {
            float x = out[1 + i];
            float sp = fmaxf(x, 0.f) + log1pf(expf(-fabsf(x)));
            acc += sp - t[i] * x;
        }
        sred[tid] = acc;
        __syncthreads();
        for (int st = 128; st > 0; st >>= 1) {
            if (tid < st) sred[tid] += sred[tid + st];
            __syncthreads();
        }
        if (tid == 0) {
            out[0] = sred[0] * (1.0f / Bn);
            d_ctr2 = 0;
        }
    }
}

// ---------------------------------------------------------------------------
extern "C" void kernel_launch(void* const* d_in, const int* in_sizes, int n_in,
                              void* d_out, int out_size) {
    const int*   tokens = (const int*)d_in[0];
    const int*   seg    = (const int*)d_in[1];
    const float* t      = (const float*)d_in[2];
    const float* emb    = (const float*)d_in[3];
    const float* W1     = (const float*)d_in[4];
    const float* b1     = (const float*)d_in[5];
    const float* gamma  = (const float*)d_in[6];
    const float* beta   = (const float*)d_in[7];
    const float* w2     = (const float*)d_in[8];
    const float* b2     = (const float*)d_in[9];
    float* out = (float*)d_out;

    static bool attrSet = false;
    if (!attrSet) {
        cudaFuncSetAttribute(gemm_kernel,
                             cudaFuncAttributeMaxDynamicSharedMemorySize, GEMM_SMEM);
        attrSet = true;
    }

    prep_kernel<<<2560 + EMB_BLKS, 256>>>(seg, W1, emb);
    bag_kernel<<<Bn, 128>>>(tokens);
    gemm_kernel<<<dim3(Bn / GM, Hn / GN), 512, GEMM_SMEM>>>(b1, gamma);
    logits_kernel<<<512, 256>>>(beta, w2, b2, t, out);
}

// round 15
// speedup vs baseline: 1.0693x; 1.0693x over previous
#include <cuda_runtime.h>
#include <cuda_bf16.h>
#include <math.h>
#include <stdint.h>

#define Tn 524288
#define Bn 4096
#define Hn 512
#define EPS 1e-5f

// Scratch (device globals)
__device__ __nv_bfloat16 d_bowh[(size_t)Bn * Hn];  // 4 MB
__device__ __nv_bfloat16 d_bowl[(size_t)Bn * Hn];  // 4 MB
__device__ __nv_bfloat16 d_W1h[(size_t)Hn * Hn];   // 512 KB
__device__ __nv_bfloat16 d_W1l[(size_t)Hn * Hn];   // 512 KB
__device__ float d_z[(size_t)Bn * Hn];             // 8 MB
__device__ float d_ps[32][Hn];
__device__ float d_pq[32][Hn];
__device__ float d_mu[Hn];
__device__ float d_A[Hn];                          // invstd * gamma
__device__ unsigned int d_ctr;                     // GEMM CTA arrival counter
__device__ unsigned int d_ctr2;                    // logits CTA arrival counter
__device__ int   d_segstart[Bn + 1];

// ---------------------------------------------------------------------------
// Kernel 0: prep = segment bounds detect + W1 -> bf16 hi/lo preconvert.
// ---------------------------------------------------------------------------
__global__ __launch_bounds__(256)
void prep_kernel(const int* __restrict__ seg, const float* __restrict__ W1) {
    if (blockIdx.x < 2048) {
        int i = blockIdx.x * 256 + threadIdx.x;
        int cur = seg[i];
        int prev = (i == 0) ? -1 : seg[i - 1];
        for (int b = prev + 1; b <= cur; b++) d_segstart[b] = i;
        if (i == Tn - 1)
            for (int b = cur + 1; b <= Bn; b++) d_segstart[b] = Tn;
    } else {
        int i = (blockIdx.x - 2048) * 256 + threadIdx.x;  // float2 id
        float2 v = ((const float2*)W1)[i];
        __nv_bfloat162 h = __floats2bfloat162_rn(v.x, v.y);
        __nv_bfloat162 l = __floats2bfloat162_rn(v.x - __bfloat162float(h.x),
                                                 v.y - __bfloat162float(h.y));
        ((__nv_bfloat162*)d_W1h)[i] = h;
        ((__nv_bfloat162*)d_W1l)[i] = l;
    }
}

// ---------------------------------------------------------------------------
// Kernel 1: embedding-bag (segment mean). One block per segment.
// ---------------------------------------------------------------------------
__global__ __launch_bounds__(128)
void bag_kernel(const int* __restrict__ tokens,
                const float* __restrict__ emb) {
    int b = blockIdx.x;
    int start = d_segstart[b];
    int end   = d_segstart[b + 1];

    int c = threadIdx.x;
    float4 acc[4];
#pragma unroll
    for (int u = 0; u < 4; u++) acc[u] = make_float4(0.f, 0.f, 0.f, 0.f);

    for (int i = start; i < end; i += 8) {
        int rem = end - i;
        int tok[8];
        float w[8];
#pragma unroll
        for (int u = 0; u < 8; u++) {
            bool ok = (u < rem);
            tok[u] = tokens[ok ? (i + u) : i];
            w[u] = ok ? 1.0f : 0.0f;
        }
        float4 v[8];
#pragma unroll
        for (int u = 0; u < 8; u++)
            v[u] = ((const float4*)(emb + (size_t)tok[u] * Hn))[c];
#pragma unroll
        for (int u = 0; u < 8; u++) {
            float4& a = acc[u & 3];
            a.x = fmaf(v[u].x, w[u], a.x);
            a.y = fmaf(v[u].y, w[u], a.y);
            a.z = fmaf(v[u].z, w[u], a.z);
            a.w = fmaf(v[u].w, w[u], a.w);
        }
    }

#pragma unroll
    for (int u = 2; u > 0; u >>= 1)
#pragma unroll
        for (int q = 0; q < u; q++) {
            acc[q].x += acc[q + u].x; acc[q].y += acc[q + u].y;
            acc[q].z += acc[q + u].z; acc[q].w += acc[q + u].w;
        }

    float inv = 1.0f / fmaxf((float)(end - start), 1.0f);
    float4 r;
    r.x = acc[0].x * inv; r.y = acc[0].y * inv;
    r.z = acc[0].z * inv; r.w = acc[0].w * inv;

    __nv_bfloat162 hxy = __floats2bfloat162_rn(r.x, r.y);
    __nv_bfloat162 hzw = __floats2bfloat162_rn(r.z, r.w);
    __nv_bfloat162 lxy = __floats2bfloat162_rn(r.x - __bfloat162float(hxy.x),
                                               r.y - __bfloat162float(hxy.y));
    __nv_bfloat162 lzw = __floats2bfloat162_rn(r.z - __bfloat162float(hzw.x),
                                               r.w - __bfloat162float(hzw.y));
    size_t base = (size_t)b * Hn + c * 4;
    *(__nv_bfloat162*)(d_bowh + base)     = hxy;
    *(__nv_bfloat162*)(d_bowh + base + 2) = hzw;
    *(__nv_bfloat162*)(d_bowl + base)     = lxy;
    *(__nv_bfloat162*)(d_bowl + base + 2) = lzw;
}

// ---------------------------------------------------------------------------
// Kernel 2: bf16 split tensor-core GEMM, single-wave (128 CTAs, 512 threads),
// 4-stage cp.async pipeline w/ single syncthreads per k-iter,
// fused column-stat partials + last-CTA stats finalize.
// ---------------------------------------------------------------------------
#define GM 128
#define GN 128
#define KT 32
#define NT_K (Hn / KT)
#define LDAS 40
#define ASZ (GM * LDAS)
#define BSZ (GN * LDAS)
#define STAGES 4
#define GEMM_SMEM ((2 * ASZ + 2 * BSZ) * STAGES * 2)   // 163840 bytes

__device__ __forceinline__ void cpa16(__nv_bfloat16* dst, const __nv_bfloat16* src) {
    uint32_t d = (uint32_t)__cvta_generic_to_shared(dst);
    asm volatile("cp.async.cg.shared.global [%0], [%1], 16;" :: "r"(d), "l"(src) : "memory");
}

__device__ __forceinline__ void ldsm_x4(uint32_t* r, const __nv_bfloat16* p) {
    uint32_t addr = (uint32_t)__cvta_generic_to_shared(p);
    asm volatile("ldmatrix.sync.aligned.m8n8.x4.shared.b16 {%0,%1,%2,%3}, [%4];"
                 : "=r"(r[0]), "=r"(r[1]), "=r"(r[2]), "=r"(r[3]) : "r"(addr));
}

__device__ __forceinline__ void mma_bf16(float* c, const uint32_t* a, const uint32_t* b) {
    asm volatile(
        "mma.sync.aligned.m16n8k16.row.col.f32.bf16.bf16.f32 "
        "{%0,%1,%2,%3}, {%4,%5,%6,%7}, {%8,%9}, {%0,%1,%2,%3};"
        : "+f"(c[0]), "+f"(c[1]), "+f"(c[2]), "+f"(c[3])
        : "r"(a[0]), "r"(a[1]), "r"(a[2]), "r"(a[3]), "r"(b[0]), "r"(b[1]));
}

__global__ __launch_bounds__(512)
void gemm_kernel(const float* __restrict__ b1, const float* __restrict__ gamma) {
    extern __shared__ __nv_bfloat16 sm[];
    __nv_bfloat16* AhB = sm;
    __nv_bfloat16* AlB = sm + STAGES * ASZ;
    __nv_bfloat16* BhB = sm + 2 * STAGES * ASZ;
    __nv_bfloat16* BlB = sm + 2 * STAGES * ASZ + STAGES * BSZ;
    __shared__ unsigned int sLast;

    int tid = threadIdx.x;
    int lane = tid & 31;
    int warp = tid >> 5;
    int wm = warp & 3;
    int wn = warp >> 2;
    int g = lane >> 2;
    int cc = lane & 3;
    int tile = lane >> 3;
    int rr = lane & 7;

    int rowBase = blockIdx.x * GM;
    int colBase = blockIdx.y * GN;

    float acc[2][4][4];
#pragma unroll
    for (int mt = 0; mt < 2; mt++)
#pragma unroll
        for (int nt = 0; nt < 4; nt++)
#pragma unroll
            for (int q = 0; q < 4; q++) acc[mt][nt][q] = 0.f;

    auto stageTile = [&](int it) {
        int buf = it % STAGES;
        int k0 = it * KT;
        __nv_bfloat16* Ah = AhB + buf * ASZ;
        __nv_bfloat16* Al = AlB + buf * ASZ;
        __nv_bfloat16* Bh = BhB + buf * BSZ;
        __nv_bfloat16* Bl = BlB + buf * BSZ;
        int r = tid >> 2;
        int q = tid & 3;
        size_t srcA = (size_t)(rowBase + r) * Hn + k0 + q * 8;
        cpa16(Ah + r * LDAS + q * 8, d_bowh + srcA);
        cpa16(Al + r * LDAS + q * 8, d_bowl + srcA);
        size_t srcB = (size_t)(colBase + r) * Hn + k0 + q * 8;
        cpa16(Bh + r * LDAS + q * 8, d_W1h + srcB);
        cpa16(Bl + r * LDAS + q * 8, d_W1l + srcB);
        asm volatile("cp.async.commit_group;" ::: "memory");
    };

    auto computeTile = [&](int it) {
        int buf = it % STAGES;
        const __nv_bfloat16* Ah = AhB + buf * ASZ;
        const __nv_bfloat16* Al = AlB + buf * ASZ;
        const __nv_bfloat16* Bh = BhB + buf * BSZ;
        const __nv_bfloat16* Bl = BlB + buf * BSZ;
#pragma unroll
        for (int kk = 0; kk < 2; kk++) {
            int kb = kk * 16;
            int ar_off = (tile & 1) * 8 + rr;
            int ak = kb + (tile >> 1) * 8;
            uint32_t afh[2][4], afl[2][4];
#pragma unroll
            for (int mt = 0; mt < 2; mt++) {
                int row = wm * 32 + mt * 16 + ar_off;
                ldsm_x4(afh[mt], Ah + row * LDAS + ak);
                ldsm_x4(afl[mt], Al + row * LDAS + ak);
            }
            int br_off = (tile >> 1) * 8 + rr;
            int bk = kb + (tile & 1) * 8;
            uint32_t bfh[2][4], bfl[2][4];
#pragma unroll
            for (int np = 0; np < 2; np++) {
                int row = wn * 32 + np * 16 + br_off;
                ldsm_x4(bfh[np], Bh + row * LDAS + bk);
                ldsm_x4(bfl[np], Bl + row * LDAS + bk);
            }
#pragma unroll
            for (int mt = 0; mt < 2; mt++)
#pragma unroll
                for (int nt = 0; nt < 4; nt++) {
                    const uint32_t* bh = &bfh[nt >> 1][(nt & 1) * 2];
                    const uint32_t* bl = &bfl[nt >> 1][(nt & 1) * 2];
                    mma_bf16(acc[mt][nt], afl[mt], bh);
                    mma_bf16(acc[mt][nt], afh[mt], bl);
                    mma_bf16(acc[mt][nt], afh[mt], bh);
                }
        }
    };

    stageTile(0);
    stageTile(1);
    stageTile(2);
    asm volatile("cp.async.wait_group 2;" ::: "memory");
    __syncthreads();

    for (int it = 0; it < NT_K; it++) {
        computeTile(it);
        if (it == NT_K - 1) break;
        if (it + 3 < NT_K) {
            stageTile(it + 3);
            asm volatile("cp.async.wait_group 2;" ::: "memory");
        } else if (it + 2 < NT_K) {
            asm volatile("cp.async.wait_group 1;" ::: "memory");
        } else {
            asm volatile("cp.async.wait_group 0;" ::: "memory");
        }
        __syncthreads();
    }
    __syncthreads();

    // ---- epilogue: bias + store z + fused column-stat partials ----
    float* sS = (float*)sm;
    float* sQ = (float*)sm + 512;

    float colS[4][2];
    float colQ[4][2];
#pragma unroll
    for (int nt = 0; nt < 4; nt++)
        colS[nt][0] = colS[nt][1] = colQ[nt][0] = colQ[nt][1] = 0.f;

#pragma unroll
    for (int mt = 0; mt < 2; mt++) {
#pragma unroll
        for (int nt = 0; nt < 4; nt++) {
            int col = colBase + wn * 32 + nt * 8 + cc * 2;
            float b0 = b1[col], b1v = b1[col + 1];
            int row0 = rowBase + wm * 32 + mt * 16 + g;
            float2 o0, o1;
            o0.x = acc[mt][nt][0] + b0;
            o0.y = acc[mt][nt][1] + b1v;
            o1.x = acc[mt][nt][2] + b0;
            o1.y = acc[mt][nt][3] + b1v;
            *(float2*)(d_z + (size_t)row0 * Hn + col) = o0;
            *(float2*)(d_z + (size_t)(row0 + 8) * Hn + col) = o1;
            colS[nt][0] += o0.x + o1.x;
            colS[nt][1] += o0.y + o1.y;
            colQ[nt][0] += o0.x * o0.x + o1.x * o1.x;
            colQ[nt][1] += o0.y * o0.y + o1.y * o1.y;
        }
    }
#pragma unroll
    for (int o = 4; o <= 16; o <<= 1) {
#pragma unroll
        for (int nt = 0; nt < 4; nt++) {
#pragma unroll
            for (int p = 0; p < 2; p++) {
                colS[nt][p] += __shfl_xor_sync(0xFFFFFFFFu, colS[nt][p], o);
                colQ[nt][p] += __shfl_xor_sync(0xFFFFFFFFu, colQ[nt][p], o);
            }
        }
    }
    if (g == 0) {
#pragma unroll
        for (int nt = 0; nt < 4; nt++) {
#pragma unroll
            for (int p = 0; p < 2; p++) {
                sS[(wn * 4 + wm) * 32 + nt * 8 + cc * 2 + p] = colS[nt][p];
                sQ[(wn * 4 + wm) * 32 + nt * 8 + cc * 2 + p] = colQ[nt][p];
            }
        }
    }
    __syncthreads();
    if (tid < GN) {
        int cwn = tid >> 5;
        int ci = tid & 31;
        float s = 0.f, q = 0.f;
#pragma unroll
        for (int y = 0; y < 4; y++) {
            s += sS[(cwn * 4 + y) * 32 + ci];
            q += sQ[(cwn * 4 + y) * 32 + ci];
        }
        d_ps[blockIdx.x][colBase + tid] = s;
        d_pq[blockIdx.x][colBase + tid] = q;
    }

    __threadfence();
    if (tid == 0) sLast = (atomicAdd(&d_ctr, 1u) == 127u) ? 1u : 0u;
    __syncthreads();
    if (sLast) {
        __threadfence();
        int c = tid;
        if (c < Hn) {
            float s = 0.f, q = 0.f;
#pragma unroll
            for (int y = 0; y < 32; y++) { s += d_ps[y][c]; q += d_pq[y][c]; }
            float mu = s * (1.0f / Bn);
            float var = q * (1.0f / Bn) - mu * mu;
            d_mu[c] = mu;
            d_A[c] = rsqrtf(var + EPS) * gamma[c];
        }
        __threadfence();
        if (tid == 0) d_ctr = 0;
    }
}

// ---------------------------------------------------------------------------
// Kernel 3: normalize + ReLU + dot(w2) -> logits, fused BCE loss in last CTA.
// 512 blocks x 256 threads; one warp per row.
// ---------------------------------------------------------------------------
__global__ __launch_bounds__(256)
void logits_kernel(const float* __restrict__ beta,
                   const float* __restrict__ w2,
                   const float* __restrict__ b2,
                   const float* __restrict__ t,
                   float* __restrict__ out) {
    __shared__ unsigned int sLast;
    __shared__ float sred[256];

    int tid = threadIdx.x;
    int warp = tid >> 5;
    int lane = tid & 31;

    int row = blockIdx.x * 8 + warp;
    const float4* zr = (const float4*)(d_z + (size_t)row * Hn);
    float sum = 0.f;
#pragma unroll
    for (int q = 0; q < 4; q++) {
        int c4 = lane + 32 * q;
        float4 z  = zr[c4];
        float4 mu = ((const float4*)d_mu)[c4];
        float4 a  = ((const float4*)d_A)[c4];
        float4 be = ((const float4*)beta)[c4];
        float4 w  = ((const float4*)w2)[c4];
        sum += fmaxf((z.x - mu.x) * a.x + be.x, 0.f) * w.x;
        sum += fmaxf((z.y - mu.y) * a.y + be.y, 0.f) * w.y;
        sum += fmaxf((z.z - mu.z) * a.z + be.z, 0.f) * w.z;
        sum += fmaxf((z.w - mu.w) * a.w + be.w, 0.f) * w.w;
    }
#pragma unroll
    for (int o = 16; o > 0; o >>= 1) sum += __shfl_xor_sync(0xFFFFFFFFu, sum, o);
    if (lane == 0) out[1 + row] = sum + b2[0];

    __threadfence();
    if (tid == 0) sLast = (atomicAdd(&d_ctr2, 1u) == 511u) ? 1u : 0u;
    __syncthreads();
    if (sLast) {
        __threadfence();
        float acc = 0.f;
#pragma unroll
        for (int i = tid; i < Bn; i += 256) {
            float x = out[1 + i];
            float sp = fmaxf(x, 0.f) + log1pf(expf(-fabsf(x)));
            acc += sp - t[i] * x;
        }
        sred[tid] = acc;
        __syncthreads();
        for (int st = 128; st > 0; st >>= 1) {
            if (tid < st) sred[tid] += sred[tid + st];
            __syncthreads();
        }
        if (tid == 0) {
            out[0] = sred[0] * (1.0f / Bn);
            d_ctr2 = 0;
        }
    }
}

// ---------------------------------------------------------------------------
extern "C" void kernel_launch(void* const* d_in, const int* in_sizes, int n_in,
                              void* d_out, int out_size) {
    const int*   tokens = (const int*)d_in[0];
    const int*   seg    = (const int*)d_in[1];
    const float* t      = (const float*)d_in[2];
    const float* emb    = (const float*)d_in[3];
    const float* W1     = (const float*)d_in[4];
    const float* b1     = (const float*)d_in[5];
    const float* gamma  = (const float*)d_in[6];
    const float* beta   = (const float*)d_in[7];
    const float* w2     = (const float*)d_in[8];
    const float* b2     = (const float*)d_in[9];
    float* out = (float*)d_out;

    static bool attrSet = false;
    if (!attrSet) {
        cudaFuncSetAttribute(gemm_kernel,
                             cudaFuncAttributeMaxDynamicSharedMemorySize, GEMM_SMEM);
        attrSet = true;
    }

    prep_kernel<<<2048 + 512, 256>>>(seg, W1);
    bag_kernel<<<Bn, 128>>>(tokens, emb);
    gemm_kernel<<<dim3(Bn / GM, Hn / GN), 512, GEMM_SMEM>>>(b1, gamma);
    logits_kernel<<<512, 256>>>(beta, w2, b2, t, out);
}